// round 3
// baseline (speedup 1.0000x reference)
#include <cuda_runtime.h>
#include <cuda_bf16.h>
#include <cstdint>

// Problem constants
#define B_DIM 16
#define P_DIM 87
#define K_DIM 4
#define N_DIM 32768
#define D_MODEL 256
#define HIDDEN 128
// (ATTN_SCALE / TAU) = (1/16) / 0.5 = 0.125
#define LOGIT_SCALE 0.125f

// Output layout (flattened tuple, fp32)
#define OUT_PROBS 0
#define OUT_LOGITS 1392
#define OUT_COORDS 2784

// Scratch (no allocations allowed -> __device__ globals)
__device__ float g_q[B_DIM * K_DIM * D_MODEL];   // projected queries
__device__ float g_acc[B_DIM * K_DIM * 4];       // per (b,k): sumw, sx, sy, sz

#define HH_BLOCKS 174   // human-head blocks, 8 rows each = 1392 rows
#define QP_BLOCKS 8     // q-proj blocks, 8 rows each = 64 rows

// ---------------------------------------------------------------------------
// Kernel 1: human MLP head (blocks 0..173, 8 rows each) +
//           q projection (blocks 174..181, 8 rows each).
// Block 174 also zeroes g_acc.
// ---------------------------------------------------------------------------
__global__ void __launch_bounds__(256)
head_qproj_kernel(const float* __restrict__ hq,
                  const float* __restrict__ oq,
                  const float* __restrict__ W1,
                  const float* __restrict__ b1,
                  const float* __restrict__ W2,
                  const float* __restrict__ b2,
                  const float* __restrict__ Wq,
                  const float* __restrict__ bq,
                  float* __restrict__ out) {
    __shared__ float xs[8 * D_MODEL];   // 8 input rows, 8 KB
    __shared__ float part[8][4];
    const int blk = blockIdx.x;
    const int t = threadIdx.x;

    if (blk < HH_BLOCKS) {
        // ---- human head: 8 rows per block ----
        const float* src = hq + (size_t)blk * 8 * D_MODEL;
#pragma unroll
        for (int j = 0; j < 8; j++)
            xs[t + j * 256] = src[t + j * 256];
        __syncthreads();

        const int g = t >> 7;        // 0: rows 0-3, 1: rows 4-7
        const int h = t & 127;       // hidden unit
        const float bb = b1[h];
        float a0 = bb, a1 = bb, a2 = bb, a3 = bb;
        const float4* x4 = reinterpret_cast<const float4*>(xs + g * 4 * 256);
#pragma unroll 4
        for (int i4 = 0; i4 < 64; i4++) {
            const float4 xa = x4[i4];
            const float4 xb = x4[64 + i4];
            const float4 xc = x4[128 + i4];
            const float4 xd = x4[192 + i4];
            const int ib = i4 * 4;
            float w;
            w = W1[(ib + 0) * 128 + h];
            a0 = fmaf(xa.x, w, a0); a1 = fmaf(xb.x, w, a1);
            a2 = fmaf(xc.x, w, a2); a3 = fmaf(xd.x, w, a3);
            w = W1[(ib + 1) * 128 + h];
            a0 = fmaf(xa.y, w, a0); a1 = fmaf(xb.y, w, a1);
            a2 = fmaf(xc.y, w, a2); a3 = fmaf(xd.y, w, a3);
            w = W1[(ib + 2) * 128 + h];
            a0 = fmaf(xa.z, w, a0); a1 = fmaf(xb.z, w, a1);
            a2 = fmaf(xc.z, w, a2); a3 = fmaf(xd.z, w, a3);
            w = W1[(ib + 3) * 128 + h];
            a0 = fmaf(xa.w, w, a0); a1 = fmaf(xb.w, w, a1);
            a2 = fmaf(xc.w, w, a2); a3 = fmaf(xd.w, w, a3);
        }
        const float w2 = W2[h];
        a0 = fmaxf(a0, 0.0f) * w2;
        a1 = fmaxf(a1, 0.0f) * w2;
        a2 = fmaxf(a2, 0.0f) * w2;
        a3 = fmaxf(a3, 0.0f) * w2;
#pragma unroll
        for (int off = 16; off > 0; off >>= 1) {
            a0 += __shfl_xor_sync(0xffffffffu, a0, off);
            a1 += __shfl_xor_sync(0xffffffffu, a1, off);
            a2 += __shfl_xor_sync(0xffffffffu, a2, off);
            a3 += __shfl_xor_sync(0xffffffffu, a3, off);
        }
        const int warp = t >> 5;
        if ((t & 31) == 0) {
            part[g * 4 + 0][warp & 3] = a0;
            part[g * 4 + 1][warp & 3] = a1;
            part[g * 4 + 2][warp & 3] = a2;
            part[g * 4 + 3][warp & 3] = a3;
        }
        __syncthreads();
        if (t < 8) {
            const float logit =
                part[t][0] + part[t][1] + part[t][2] + part[t][3] + b2[0];
            const int row = blk * 8 + t;
            out[OUT_LOGITS + row] = logit;
            out[OUT_PROBS + row] = 1.0f / (1.0f + __expf(-logit));
        }
    } else {
        // ---- q projection: 8 (b,k) rows per block ----
        const int qb = blk - HH_BLOCKS;  // 0..7
        const float* src = oq + (size_t)qb * 8 * D_MODEL;
#pragma unroll
        for (int j = 0; j < 8; j++)
            xs[t + j * 256] = src[t + j * 256];
        if (qb == 0) g_acc[t] = 0.0f;    // 256 floats == blockDim
        __syncthreads();

        float acc[8];
        const float bv = bq[t];
#pragma unroll
        for (int r = 0; r < 8; r++) acc[r] = bv;
        const float4* x4 = reinterpret_cast<const float4*>(xs);
#pragma unroll 2
        for (int i4 = 0; i4 < 64; i4++) {
            float4 xr[8];
#pragma unroll
            for (int r = 0; r < 8; r++) xr[r] = x4[r * 64 + i4];
            const int ib = i4 * 4;
            float w;
            w = Wq[(ib + 0) * 256 + t];
#pragma unroll
            for (int r = 0; r < 8; r++) acc[r] = fmaf(xr[r].x, w, acc[r]);
            w = Wq[(ib + 1) * 256 + t];
#pragma unroll
            for (int r = 0; r < 8; r++) acc[r] = fmaf(xr[r].y, w, acc[r]);
            w = Wq[(ib + 2) * 256 + t];
#pragma unroll
            for (int r = 0; r < 8; r++) acc[r] = fmaf(xr[r].z, w, acc[r]);
            w = Wq[(ib + 3) * 256 + t];
#pragma unroll
            for (int r = 0; r < 8; r++) acc[r] = fmaf(xr[r].w, w, acc[r]);
        }
#pragma unroll
        for (int r = 0; r < 8; r++)
            g_q[(size_t)(qb * 8 + r) * D_MODEL + t] = acc[r];
    }
}

// ---------------------------------------------------------------------------
// Kernel 2: attention pooling mainloop.
// grid = (N/256, B), block = 256 (8 warps, 32 rows/warp).
// Coalesced float4 loads; quad-transpose reduction (7 SHFL/row);
// batched exp (one full-warp __expf per 8 rows).
// ---------------------------------------------------------------------------
__global__ void __launch_bounds__(256)
attn_pool_kernel(const float* __restrict__ feats,
                 const float* __restrict__ xyz) {
    const int b = blockIdx.y;
    const int warp = threadIdx.x >> 5;
    const int lane = threadIdx.x & 31;
    const int seg = lane >> 2;          // 0..7: which row of the 8-row batch
    const int row0 = blockIdx.x * 256 + warp * 32;

    // q in registers: lane covers elems [4*lane,4*lane+4) and [128+4*lane,...)
    const float4* q4 =
        reinterpret_cast<const float4*>(g_q + (size_t)b * K_DIM * D_MODEL);
    float4 qa[K_DIM], qb[K_DIM];
#pragma unroll
    for (int k = 0; k < K_DIM; k++) {
        qa[k] = q4[k * 64 + lane];
        qb[k] = q4[k * 64 + 32 + lane];
    }

    const float4* f4 = reinterpret_cast<const float4*>(
        feats + ((size_t)b * N_DIM + row0) * D_MODEL);

    float aw = 0.0f, ax = 0.0f, ay = 0.0f, az = 0.0f;

#pragma unroll
    for (int batch = 0; batch < 4; batch++) {
        float keep = 0.0f;
#pragma unroll
        for (int rb = 0; rb < 8; rb++) {
            const int row = batch * 8 + rb;   // 0..31 within warp's range
            const float4 fa = f4[(size_t)row * 64 + lane];
            const float4 fb = f4[(size_t)row * 64 + 32 + lane];

            float p0, p1, p2, p3;
            p0 = fa.x * qa[0].x; p0 = fmaf(fa.y, qa[0].y, p0);
            p0 = fmaf(fa.z, qa[0].z, p0); p0 = fmaf(fa.w, qa[0].w, p0);
            p0 = fmaf(fb.x, qb[0].x, p0); p0 = fmaf(fb.y, qb[0].y, p0);
            p0 = fmaf(fb.z, qb[0].z, p0); p0 = fmaf(fb.w, qb[0].w, p0);

            p1 = fa.x * qa[1].x; p1 = fmaf(fa.y, qa[1].y, p1);
            p1 = fmaf(fa.z, qa[1].z, p1); p1 = fmaf(fa.w, qa[1].w, p1);
            p1 = fmaf(fb.x, qb[1].x, p1); p1 = fmaf(fb.y, qb[1].y, p1);
            p1 = fmaf(fb.z, qb[1].z, p1); p1 = fmaf(fb.w, qb[1].w, p1);

            p2 = fa.x * qa[2].x; p2 = fmaf(fa.y, qa[2].y, p2);
            p2 = fmaf(fa.z, qa[2].z, p2); p2 = fmaf(fa.w, qa[2].w, p2);
            p2 = fmaf(fb.x, qb[2].x, p2); p2 = fmaf(fb.y, qb[2].y, p2);
            p2 = fmaf(fb.z, qb[2].z, p2); p2 = fmaf(fb.w, qb[2].w, p2);

            p3 = fa.x * qa[3].x; p3 = fmaf(fa.y, qa[3].y, p3);
            p3 = fmaf(fa.z, qa[3].z, p3); p3 = fmaf(fa.w, qa[3].w, p3);
            p3 = fmaf(fb.x, qb[3].x, p3); p3 = fmaf(fb.y, qb[3].y, p3);
            p3 = fmaf(fb.z, qb[3].z, p3); p3 = fmaf(fb.w, qb[3].w, p3);

            // Quad transpose-reduce: lane ends holding sum for k = lane&3
            float t1 = (lane & 1) ? p0 : p1;
            t1 = __shfl_xor_sync(0xffffffffu, t1, 1);
            float t2 = (lane & 1) ? p2 : p3;
            t2 = __shfl_xor_sync(0xffffffffu, t2, 1);
            const float aab = ((lane & 1) ? p1 : p0) + t1;
            const float ccd = ((lane & 1) ? p3 : p2) + t2;
            float t3 = (lane & 2) ? aab : ccd;
            t3 = __shfl_xor_sync(0xffffffffu, t3, 2);
            float v = ((lane & 2) ? ccd : aab) + t3;
            // Reduce across the 8 quads
            v += __shfl_xor_sync(0xffffffffu, v, 4);
            v += __shfl_xor_sync(0xffffffffu, v, 8);
            v += __shfl_xor_sync(0xffffffffu, v, 16);
            // lane (4*rb + k) keeps logit(row rb, k)
            if (seg == rb) keep = v;
        }

        // One full-warp exp per 8 rows
        const float wv = __expf(keep * LOGIT_SCALE);
        const float* xp =
            xyz + ((size_t)b * N_DIM + row0 + batch * 8) * 3;
        const float px = xp[seg * 3 + 0];
        const float py = xp[seg * 3 + 1];
        const float pz = xp[seg * 3 + 2];
        aw += wv;
        ax = fmaf(wv, px, ax);
        ay = fmaf(wv, py, ay);
        az = fmaf(wv, pz, az);
    }

    // Reduce across lanes sharing the same k (lanes differ in bits 2..4)
#pragma unroll
    for (int off = 4; off < 32; off <<= 1) {
        aw += __shfl_xor_sync(0xffffffffu, aw, off);
        ax += __shfl_xor_sync(0xffffffffu, ax, off);
        ay += __shfl_xor_sync(0xffffffffu, ay, off);
        az += __shfl_xor_sync(0xffffffffu, az, off);
    }
    if (lane < K_DIM) {
        float* g = g_acc + ((size_t)b * K_DIM + lane) * 4;
        atomicAdd(g + 0, aw);
        atomicAdd(g + 1, ax);
        atomicAdd(g + 2, ay);
        atomicAdd(g + 3, az);
    }
}

// ---------------------------------------------------------------------------
// Kernel 3: finalize coords = (sum w*xyz) / (sum w)
// ---------------------------------------------------------------------------
__global__ void finalize_kernel(float* __restrict__ out) {
    const int t = threadIdx.x;  // 0..63 = (b*4 + k)
    if (t < B_DIM * K_DIM) {
        const float* g = g_acc + (size_t)t * 4;
        const float inv = 1.0f / g[0];
        out[OUT_COORDS + t * 3 + 0] = g[1] * inv;
        out[OUT_COORDS + t * 3 + 1] = g[2] * inv;
        out[OUT_COORDS + t * 3 + 2] = g[3] * inv;
    }
}

// ---------------------------------------------------------------------------
extern "C" void kernel_launch(void* const* d_in, const int* in_sizes, int n_in,
                              void* d_out, int out_size) {
    const float* hq    = (const float*)d_in[0];  // (16, 87, 256)
    const float* oq    = (const float*)d_in[1];  // (16, 4, 256)
    const float* feats = (const float*)d_in[2];  // (16, 32768, 256)
    const float* xyz   = (const float*)d_in[3];  // (16, 32768, 3)
    const float* W1    = (const float*)d_in[4];  // (256, 128)
    const float* b1    = (const float*)d_in[5];  // (128,)
    const float* W2    = (const float*)d_in[6];  // (128, 1)
    const float* b2    = (const float*)d_in[7];  // (1,)
    const float* Wq    = (const float*)d_in[8];  // (256, 256)
    const float* bq    = (const float*)d_in[9];  // (256,)
    float* out = (float*)d_out;

    head_qproj_kernel<<<HH_BLOCKS + QP_BLOCKS, 256>>>(
        hq, oq, W1, b1, W2, b2, Wq, bq, out);

    dim3 grid(N_DIM / 256, B_DIM);  // (128, 16)
    attn_pool_kernel<<<grid, 256>>>(feats, xyz);

    finalize_kernel<<<1, 64>>>(out);
}

// round 4
// speedup vs baseline: 1.9199x; 1.9199x over previous
#include <cuda_runtime.h>
#include <cuda_bf16.h>
#include <cstdint>

// Problem constants
#define B_DIM 16
#define P_DIM 87
#define K_DIM 4
#define N_DIM 32768
#define D_MODEL 256
#define HIDDEN 128
#define LOGIT_SCALE 0.125f   // ATTN_SCALE / TAU

// Output layout (flattened tuple, fp32)
#define OUT_PROBS 0
#define OUT_LOGITS 1392
#define OUT_COORDS 2784

// Scratch (no allocations allowed -> __device__ globals)
__device__ float g_q[B_DIM * K_DIM * D_MODEL];   // projected queries
__device__ float g_acc[B_DIM * K_DIM * 4];       // per (b,k): sumw, sx, sy, sz

#define HH_BLOCKS 348   // human-head blocks, 4 rows each = 1392 rows
#define QP_BLOCKS 16    // q-proj blocks, 4 rows each = 64 rows

// ---------------------------------------------------------------------------
// cp.async helpers
// ---------------------------------------------------------------------------
__device__ __forceinline__ void cp16(void* dst, const void* src) {
    uint32_t d = (uint32_t)__cvta_generic_to_shared(dst);
    asm volatile("cp.async.cg.shared.global [%0], [%1], 16;" :: "r"(d), "l"(src));
}
__device__ __forceinline__ void cp4(void* dst, const void* src) {
    uint32_t d = (uint32_t)__cvta_generic_to_shared(dst);
    asm volatile("cp.async.ca.shared.global [%0], [%1], 4;" :: "r"(d), "l"(src));
}
__device__ __forceinline__ void cp_commit() {
    asm volatile("cp.async.commit_group;");
}

// ---------------------------------------------------------------------------
// Kernel 1: human MLP head (blocks 0..347, 4 rows each) +
//           q projection (blocks 348..363, 4 rows each).
// Warps partition the reduction (i) dimension; weight loads are coalesced
// float4 with long FMA runs between consumption (hoistable by ptxas).
// ---------------------------------------------------------------------------
__global__ void __launch_bounds__(256)
head_qproj_kernel(const float* __restrict__ hq,
                  const float* __restrict__ oq,
                  const float* __restrict__ W1,
                  const float* __restrict__ b1,
                  const float* __restrict__ W2,
                  const float* __restrict__ b2,
                  const float* __restrict__ Wq,
                  const float* __restrict__ bq,
                  float* __restrict__ out) {
    __shared__ float xs[4 * D_MODEL];     // 4 input rows (4 KB)
    __shared__ float4 part4[2048];        // warp partials (32 KB)
    const int blk = blockIdx.x;
    const int t = threadIdx.x;
    const int w = t >> 5;
    const int lane = t & 31;

    if (blk < HH_BLOCKS) {
        // ---- human head: 4 rows ----
        const float* src = hq + (size_t)blk * 4 * D_MODEL;
#pragma unroll
        for (int j = 0; j < 4; j++) xs[t + j * 256] = src[t + j * 256];
        __syncthreads();

        // warp w owns i in [w*32, w*32+32); lane owns hidden h4 = 4*lane
        const int i0 = w * 32;
        const float4* w1v = reinterpret_cast<const float4*>(W1);
        float4 a0 = {0,0,0,0}, a1 = {0,0,0,0}, a2 = {0,0,0,0}, a3 = {0,0,0,0};
#pragma unroll 4
        for (int ii = 0; ii < 32; ii++) {
            const int i = i0 + ii;
            const float4 wv = w1v[i * 32 + lane];
            const float x0 = xs[i];
            const float x1 = xs[256 + i];
            const float x2 = xs[512 + i];
            const float x3 = xs[768 + i];
            a0.x = fmaf(x0, wv.x, a0.x); a0.y = fmaf(x0, wv.y, a0.y);
            a0.z = fmaf(x0, wv.z, a0.z); a0.w = fmaf(x0, wv.w, a0.w);
            a1.x = fmaf(x1, wv.x, a1.x); a1.y = fmaf(x1, wv.y, a1.y);
            a1.z = fmaf(x1, wv.z, a1.z); a1.w = fmaf(x1, wv.w, a1.w);
            a2.x = fmaf(x2, wv.x, a2.x); a2.y = fmaf(x2, wv.y, a2.y);
            a2.z = fmaf(x2, wv.z, a2.z); a2.w = fmaf(x2, wv.w, a2.w);
            a3.x = fmaf(x3, wv.x, a3.x); a3.y = fmaf(x3, wv.y, a3.y);
            a3.z = fmaf(x3, wv.z, a3.z); a3.w = fmaf(x3, wv.w, a3.w);
        }
        part4[(w * 4 + 0) * 32 + lane] = a0;
        part4[(w * 4 + 1) * 32 + lane] = a1;
        part4[(w * 4 + 2) * 32 + lane] = a2;
        part4[(w * 4 + 3) * 32 + lane] = a3;
        __syncthreads();

        if (t < 128) {
            const int r = t >> 5;      // row
            const int l = t & 31;      // lane -> h4 = 4*l
            float4 s = part4[r * 32 + l];
#pragma unroll
            for (int j = 1; j < 8; j++) {
                const float4 p = part4[(j * 4 + r) * 32 + l];
                s.x += p.x; s.y += p.y; s.z += p.z; s.w += p.w;
            }
            const float4 bb = reinterpret_cast<const float4*>(b1)[l];
            s.x = fmaxf(s.x + bb.x, 0.0f);
            s.y = fmaxf(s.y + bb.y, 0.0f);
            s.z = fmaxf(s.z + bb.z, 0.0f);
            s.w = fmaxf(s.w + bb.w, 0.0f);
            const float4 w2 = reinterpret_cast<const float4*>(W2)[l];
            float v = s.x * w2.x + s.y * w2.y + s.z * w2.z + s.w * w2.w;
#pragma unroll
            for (int off = 16; off > 0; off >>= 1)
                v += __shfl_xor_sync(0xffffffffu, v, off);
            if (l == 0) {
                const int row = blk * 4 + r;
                const float logit = v + b2[0];
                out[OUT_LOGITS + row] = logit;
                out[OUT_PROBS + row] = 1.0f / (1.0f + __expf(-logit));
            }
        }
    } else {
        // ---- q projection: 4 rows ----
        const int qb = blk - HH_BLOCKS;   // 0..15
        const float* src = oq + (size_t)qb * 4 * D_MODEL;
#pragma unroll
        for (int j = 0; j < 4; j++) xs[t + j * 256] = src[t + j * 256];
        if (qb == 0) g_acc[t] = 0.0f;     // 256 floats == blockDim
        __syncthreads();

        // warp w owns i in [w*32, w*32+32); lane owns outputs 4*lane and 128+4*lane
        const int i0 = w * 32;
        const float4* wqv = reinterpret_cast<const float4*>(Wq);
        float4 aA[4], aB[4];
#pragma unroll
        for (int r = 0; r < 4; r++) { aA[r] = {0,0,0,0}; aB[r] = {0,0,0,0}; }
#pragma unroll 4
        for (int ii = 0; ii < 32; ii++) {
            const int i = i0 + ii;
            const float4 wa = wqv[i * 64 + lane];
            const float4 wb = wqv[i * 64 + 32 + lane];
            const float x0 = xs[i];
            const float x1 = xs[256 + i];
            const float x2 = xs[512 + i];
            const float x3 = xs[768 + i];
            aA[0].x = fmaf(x0, wa.x, aA[0].x); aA[0].y = fmaf(x0, wa.y, aA[0].y);
            aA[0].z = fmaf(x0, wa.z, aA[0].z); aA[0].w = fmaf(x0, wa.w, aA[0].w);
            aB[0].x = fmaf(x0, wb.x, aB[0].x); aB[0].y = fmaf(x0, wb.y, aB[0].y);
            aB[0].z = fmaf(x0, wb.z, aB[0].z); aB[0].w = fmaf(x0, wb.w, aB[0].w);
            aA[1].x = fmaf(x1, wa.x, aA[1].x); aA[1].y = fmaf(x1, wa.y, aA[1].y);
            aA[1].z = fmaf(x1, wa.z, aA[1].z); aA[1].w = fmaf(x1, wa.w, aA[1].w);
            aB[1].x = fmaf(x1, wb.x, aB[1].x); aB[1].y = fmaf(x1, wb.y, aB[1].y);
            aB[1].z = fmaf(x1, wb.z, aB[1].z); aB[1].w = fmaf(x1, wb.w, aB[1].w);
            aA[2].x = fmaf(x2, wa.x, aA[2].x); aA[2].y = fmaf(x2, wa.y, aA[2].y);
            aA[2].z = fmaf(x2, wa.z, aA[2].z); aA[2].w = fmaf(x2, wa.w, aA[2].w);
            aB[2].x = fmaf(x2, wb.x, aB[2].x); aB[2].y = fmaf(x2, wb.y, aB[2].y);
            aB[2].z = fmaf(x2, wb.z, aB[2].z); aB[2].w = fmaf(x2, wb.w, aB[2].w);
            aA[3].x = fmaf(x3, wa.x, aA[3].x); aA[3].y = fmaf(x3, wa.y, aA[3].y);
            aA[3].z = fmaf(x3, wa.z, aA[3].z); aA[3].w = fmaf(x3, wa.w, aA[3].w);
            aB[3].x = fmaf(x3, wb.x, aB[3].x); aB[3].y = fmaf(x3, wb.y, aB[3].y);
            aB[3].z = fmaf(x3, wb.z, aB[3].z); aB[3].w = fmaf(x3, wb.w, aB[3].w);
        }
#pragma unroll
        for (int r = 0; r < 4; r++) {
            part4[(w * 4 + r) * 64 + lane] = aA[r];
            part4[(w * 4 + r) * 64 + 32 + lane] = aB[r];
        }
        __syncthreads();

        // 256 float4 outputs; thread t -> (row r = t>>6, col c = t&63)
        const int r = t >> 6;
        const int c = t & 63;
        float4 s = part4[r * 64 + c];
#pragma unroll
        for (int j = 1; j < 8; j++) {
            const float4 p = part4[(j * 4 + r) * 64 + c];
            s.x += p.x; s.y += p.y; s.z += p.z; s.w += p.w;
        }
        const float4 bb = reinterpret_cast<const float4*>(bq)[c];
        s.x += bb.x; s.y += bb.y; s.z += bb.z; s.w += bb.w;
        reinterpret_cast<float4*>(g_q + (size_t)(qb * 4 + r) * D_MODEL)[c] = s;
    }
}

// ---------------------------------------------------------------------------
// Kernel 2: attention pooling, cp.async double-buffered pipeline.
// grid (N/256, B), block 256. Tile = 32 rows (32 KB), 2 buffers.
// Warp handles 4 rows/tile; quad-transpose reduce; exp batched per 4 rows.
// ---------------------------------------------------------------------------
#define TR 32
#define NT 8
#define ATTN_SMEM_BYTES (2*TR*256*4 + 2*TR*3*4 + 32*16)  // 65536+768+512=66816

__global__ void __launch_bounds__(256, 3)
attn_pool_kernel(const float* __restrict__ feats,
                 const float* __restrict__ xyz) {
    extern __shared__ float sm[];
    float* buf = sm;                              // 2 * 8192 floats
    float* xyzs = sm + 2 * TR * 256;              // 2 * 96 floats
    float4* red4 = reinterpret_cast<float4*>(sm + 2 * TR * 256 + 2 * TR * 3);

    const int b = blockIdx.y;
    const int t = threadIdx.x;
    const int warp = t >> 5;
    const int lane = t & 31;
    const int row0 = blockIdx.x * (TR * NT);

    // q in registers
    const float4* q4 =
        reinterpret_cast<const float4*>(g_q + (size_t)b * K_DIM * D_MODEL);
    float4 qa[K_DIM], qb[K_DIM];
#pragma unroll
    for (int k = 0; k < K_DIM; k++) {
        qa[k] = q4[k * 64 + lane];
        qb[k] = q4[k * 64 + 32 + lane];
    }

    const float* fbase = feats + ((size_t)b * N_DIM + row0) * D_MODEL;
    const float* xbase = xyz + ((size_t)b * N_DIM + row0) * 3;

    // prologue: issue tiles 0 and 1
#pragma unroll
    for (int pt = 0; pt < 2; pt++) {
        const float* src = fbase + pt * TR * 256;
        float* dst = buf + pt * TR * 256;
#pragma unroll
        for (int j = 0; j < 8; j++) {
            const int f = (t + j * 256) * 4;
            cp16(dst + f, src + f);
        }
        if (t < TR * 3) cp4(xyzs + pt * TR * 3 + t, xbase + pt * TR * 3 + t);
        cp_commit();
    }

    float aw = 0.0f, ax = 0.0f, ay = 0.0f, az = 0.0f;
    const int myrow = (lane >> 2) & 3;   // which of the 4 rows this lane exps

#pragma unroll 1
    for (int tile = 0; tile < NT; tile++) {
        if (tile < NT - 1) asm volatile("cp.async.wait_group 1;");
        else               asm volatile("cp.async.wait_group 0;");
        __syncthreads();

        const int bi = tile & 1;
        const float4* B4 = reinterpret_cast<const float4*>(buf + bi * TR * 256);
        const float* XZ = xyzs + bi * TR * 3;

        float keep = 0.0f;
#pragma unroll
        for (int rb = 0; rb < 4; rb++) {
            const int row = warp * 4 + rb;
            const float4 fa = B4[row * 64 + lane];
            const float4 fb = B4[row * 64 + 32 + lane];

            float p0, p1, p2, p3;
            p0 = fa.x * qa[0].x; p0 = fmaf(fa.y, qa[0].y, p0);
            p0 = fmaf(fa.z, qa[0].z, p0); p0 = fmaf(fa.w, qa[0].w, p0);
            p0 = fmaf(fb.x, qb[0].x, p0); p0 = fmaf(fb.y, qb[0].y, p0);
            p0 = fmaf(fb.z, qb[0].z, p0); p0 = fmaf(fb.w, qb[0].w, p0);

            p1 = fa.x * qa[1].x; p1 = fmaf(fa.y, qa[1].y, p1);
            p1 = fmaf(fa.z, qa[1].z, p1); p1 = fmaf(fa.w, qa[1].w, p1);
            p1 = fmaf(fb.x, qb[1].x, p1); p1 = fmaf(fb.y, qb[1].y, p1);
            p1 = fmaf(fb.z, qb[1].z, p1); p1 = fmaf(fb.w, qb[1].w, p1);

            p2 = fa.x * qa[2].x; p2 = fmaf(fa.y, qa[2].y, p2);
            p2 = fmaf(fa.z, qa[2].z, p2); p2 = fmaf(fa.w, qa[2].w, p2);
            p2 = fmaf(fb.x, qb[2].x, p2); p2 = fmaf(fb.y, qb[2].y, p2);
            p2 = fmaf(fb.z, qb[2].z, p2); p2 = fmaf(fb.w, qb[2].w, p2);

            p3 = fa.x * qa[3].x; p3 = fmaf(fa.y, qa[3].y, p3);
            p3 = fmaf(fa.z, qa[3].z, p3); p3 = fmaf(fa.w, qa[3].w, p3);
            p3 = fmaf(fb.x, qb[3].x, p3); p3 = fmaf(fb.y, qb[3].y, p3);
            p3 = fmaf(fb.z, qb[3].z, p3); p3 = fmaf(fb.w, qb[3].w, p3);

            // Quad transpose-reduce: every lane ends with sum for k = lane&3
            float t1 = (lane & 1) ? p0 : p1;
            t1 = __shfl_xor_sync(0xffffffffu, t1, 1);
            float t2 = (lane & 1) ? p2 : p3;
            t2 = __shfl_xor_sync(0xffffffffu, t2, 1);
            const float aab = ((lane & 1) ? p1 : p0) + t1;
            const float ccd = ((lane & 1) ? p3 : p2) + t2;
            float t3 = (lane & 2) ? aab : ccd;
            t3 = __shfl_xor_sync(0xffffffffu, t3, 2);
            float v = ((lane & 2) ? ccd : aab) + t3;
            v += __shfl_xor_sync(0xffffffffu, v, 4);
            v += __shfl_xor_sync(0xffffffffu, v, 8);
            v += __shfl_xor_sync(0xffffffffu, v, 16);
            if (myrow == rb) keep = v;
        }

        // one exp per 4 rows; lanes < 16 accumulate (lane = 4*row + k)
        const float wgt = __expf(keep * LOGIT_SCALE);
        if (lane < 16) {
            const int row = warp * 4 + myrow;
            const float px = XZ[row * 3 + 0];
            const float py = XZ[row * 3 + 1];
            const float pz = XZ[row * 3 + 2];
            aw += wgt;
            ax = fmaf(wgt, px, ax);
            ay = fmaf(wgt, py, ay);
            az = fmaf(wgt, pz, az);
        }

        __syncthreads();   // everyone done reading buf[bi] before refill

        if (tile + 2 < NT) {
            const float* src = fbase + (tile + 2) * TR * 256;
            float* dst = buf + bi * TR * 256;
#pragma unroll
            for (int j = 0; j < 8; j++) {
                const int f = (t + j * 256) * 4;
                cp16(dst + f, src + f);
            }
            if (t < TR * 3)
                cp4(xyzs + bi * TR * 3 + t, xbase + (tile + 2) * TR * 3 + t);
            cp_commit();
        }
    }

    // reduce within warp: lanes sharing k (k = lane&3); upper lanes hold zeros
#pragma unroll
    for (int off = 4; off < 32; off <<= 1) {
        aw += __shfl_xor_sync(0xffffffffu, aw, off);
        ax += __shfl_xor_sync(0xffffffffu, ax, off);
        ay += __shfl_xor_sync(0xffffffffu, ay, off);
        az += __shfl_xor_sync(0xffffffffu, az, off);
    }
    if (lane < 4)
        red4[warp * 4 + lane] = make_float4(aw, ax, ay, az);
    __syncthreads();

    if (t < 16) {
        const int k = t >> 2;
        const int c = t & 3;
        const float* rf = reinterpret_cast<const float*>(red4);
        float s = 0.0f;
#pragma unroll
        for (int j = 0; j < 8; j++) s += rf[(j * 4 + k) * 4 + c];
        atomicAdd(&g_acc[((size_t)b * K_DIM + k) * 4 + c], s);
    }
}

// ---------------------------------------------------------------------------
// Kernel 3: finalize coords = (sum w*xyz) / (sum w)
// ---------------------------------------------------------------------------
__global__ void finalize_kernel(float* __restrict__ out) {
    const int t = threadIdx.x;  // 0..63 = (b*4 + k)
    if (t < B_DIM * K_DIM) {
        const float* g = g_acc + (size_t)t * 4;
        const float inv = 1.0f / g[0];
        out[OUT_COORDS + t * 3 + 0] = g[1] * inv;
        out[OUT_COORDS + t * 3 + 1] = g[2] * inv;
        out[OUT_COORDS + t * 3 + 2] = g[3] * inv;
    }
}

// ---------------------------------------------------------------------------
extern "C" void kernel_launch(void* const* d_in, const int* in_sizes, int n_in,
                              void* d_out, int out_size) {
    const float* hq    = (const float*)d_in[0];
    const float* oq    = (const float*)d_in[1];
    const float* feats = (const float*)d_in[2];
    const float* xyz   = (const float*)d_in[3];
    const float* W1    = (const float*)d_in[4];
    const float* b1    = (const float*)d_in[5];
    const float* W2    = (const float*)d_in[6];
    const float* b2    = (const float*)d_in[7];
    const float* Wq    = (const float*)d_in[8];
    const float* bq    = (const float*)d_in[9];
    float* out = (float*)d_out;

    cudaFuncSetAttribute(attn_pool_kernel,
                         cudaFuncAttributeMaxDynamicSharedMemorySize,
                         ATTN_SMEM_BYTES);

    head_qproj_kernel<<<HH_BLOCKS + QP_BLOCKS, 256>>>(
        hq, oq, W1, b1, W2, b2, Wq, bq, out);

    dim3 grid(N_DIM / (TR * NT), B_DIM);  // (128, 16)
    attn_pool_kernel<<<grid, 256, ATTN_SMEM_BYTES>>>(feats, xyz);

    finalize_kernel<<<1, 64>>>(out);
}

// round 5
// speedup vs baseline: 1.9601x; 1.0209x over previous
#include <cuda_runtime.h>
#include <cuda_bf16.h>
#include <cstdint>

// Problem constants
#define B_DIM 16
#define P_DIM 87
#define K_DIM 4
#define N_DIM 32768
#define D_MODEL 256
#define HIDDEN 128
#define LOGIT_SCALE 0.125f   // ATTN_SCALE / TAU

// Output layout (flattened tuple, fp32)
#define OUT_PROBS 0
#define OUT_LOGITS 1392
#define OUT_COORDS 2784

// Scratch (no allocations allowed -> __device__ globals)
__device__ float g_q[B_DIM * K_DIM * D_MODEL];   // projected queries
__device__ float g_acc[B_DIM * K_DIM * 4];       // per (b,k): sumw, sx, sy, sz

#define HH_BLOCKS 348       // human-head blocks, 4 rows each = 1392 rows
#define QP_BLOCKS 16        // q-proj blocks, 4 rows each = 64 rows
#define ATTN_BLOCKS 2048    // 128 x-tiles * 16 batches

// ---------------------------------------------------------------------------
// cp.async helpers
// ---------------------------------------------------------------------------
__device__ __forceinline__ void cp16(void* dst, const void* src) {
    uint32_t d = (uint32_t)__cvta_generic_to_shared(dst);
    asm volatile("cp.async.cg.shared.global [%0], [%1], 16;" :: "r"(d), "l"(src));
}
__device__ __forceinline__ void cp4(void* dst, const void* src) {
    uint32_t d = (uint32_t)__cvta_generic_to_shared(dst);
    asm volatile("cp.async.ca.shared.global [%0], [%1], 4;" :: "r"(d), "l"(src));
}
__device__ __forceinline__ void cp_commit() {
    asm volatile("cp.async.commit_group;");
}

// ---------------------------------------------------------------------------
// Kernel 1: q projection only (16 blocks, 4 rows each) + zero g_acc.
// Must run before the fused kernel (attn reads g_q).
// ---------------------------------------------------------------------------
__global__ void __launch_bounds__(256)
qproj_kernel(const float* __restrict__ oq,
             const float* __restrict__ Wq,
             const float* __restrict__ bq) {
    __shared__ float xs[4 * D_MODEL];
    __shared__ float4 part4[2048];
    const int qb = blockIdx.x;       // 0..15
    const int t = threadIdx.x;
    const int w = t >> 5;
    const int lane = t & 31;

    const float* src = oq + (size_t)qb * 4 * D_MODEL;
#pragma unroll
    for (int j = 0; j < 4; j++) xs[t + j * 256] = src[t + j * 256];
    if (qb == 0) g_acc[t] = 0.0f;    // 256 floats == blockDim
    __syncthreads();

    const int i0 = w * 32;
    const float4* wqv = reinterpret_cast<const float4*>(Wq);
    float4 aA[4], aB[4];
#pragma unroll
    for (int r = 0; r < 4; r++) { aA[r] = {0,0,0,0}; aB[r] = {0,0,0,0}; }
#pragma unroll 4
    for (int ii = 0; ii < 32; ii++) {
        const int i = i0 + ii;
        const float4 wa = wqv[i * 64 + lane];
        const float4 wb = wqv[i * 64 + 32 + lane];
        const float x0 = xs[i];
        const float x1 = xs[256 + i];
        const float x2 = xs[512 + i];
        const float x3 = xs[768 + i];
        aA[0].x = fmaf(x0, wa.x, aA[0].x); aA[0].y = fmaf(x0, wa.y, aA[0].y);
        aA[0].z = fmaf(x0, wa.z, aA[0].z); aA[0].w = fmaf(x0, wa.w, aA[0].w);
        aB[0].x = fmaf(x0, wb.x, aB[0].x); aB[0].y = fmaf(x0, wb.y, aB[0].y);
        aB[0].z = fmaf(x0, wb.z, aB[0].z); aB[0].w = fmaf(x0, wb.w, aB[0].w);
        aA[1].x = fmaf(x1, wa.x, aA[1].x); aA[1].y = fmaf(x1, wa.y, aA[1].y);
        aA[1].z = fmaf(x1, wa.z, aA[1].z); aA[1].w = fmaf(x1, wa.w, aA[1].w);
        aB[1].x = fmaf(x1, wb.x, aB[1].x); aB[1].y = fmaf(x1, wb.y, aB[1].y);
        aB[1].z = fmaf(x1, wb.z, aB[1].z); aB[1].w = fmaf(x1, wb.w, aB[1].w);
        aA[2].x = fmaf(x2, wa.x, aA[2].x); aA[2].y = fmaf(x2, wa.y, aA[2].y);
        aA[2].z = fmaf(x2, wa.z, aA[2].z); aA[2].w = fmaf(x2, wa.w, aA[2].w);
        aB[2].x = fmaf(x2, wb.x, aB[2].x); aB[2].y = fmaf(x2, wb.y, aB[2].y);
        aB[2].z = fmaf(x2, wb.z, aB[2].z); aB[2].w = fmaf(x2, wb.w, aB[2].w);
        aA[3].x = fmaf(x3, wa.x, aA[3].x); aA[3].y = fmaf(x3, wa.y, aA[3].y);
        aA[3].z = fmaf(x3, wa.z, aA[3].z); aA[3].w = fmaf(x3, wa.w, aA[3].w);
        aB[3].x = fmaf(x3, wb.x, aB[3].x); aB[3].y = fmaf(x3, wb.y, aB[3].y);
        aB[3].z = fmaf(x3, wb.z, aB[3].z); aB[3].w = fmaf(x3, wb.w, aB[3].w);
    }
#pragma unroll
    for (int r = 0; r < 4; r++) {
        part4[(w * 4 + r) * 64 + lane] = aA[r];
        part4[(w * 4 + r) * 64 + 32 + lane] = aB[r];
    }
    __syncthreads();

    const int r = t >> 6;
    const int c = t & 63;
    float4 s = part4[r * 64 + c];
#pragma unroll
    for (int j = 1; j < 8; j++) {
        const float4 p = part4[(j * 4 + r) * 64 + c];
        s.x += p.x; s.y += p.y; s.z += p.z; s.w += p.w;
    }
    const float4 bb = reinterpret_cast<const float4*>(bq)[c];
    s.x += bb.x; s.y += bb.y; s.z += bb.z; s.w += bb.w;
    reinterpret_cast<float4*>(g_q + (size_t)(qb * 4 + r) * D_MODEL)[c] = s;
}

// ---------------------------------------------------------------------------
// Kernel 2 (fused): blocks [0, HH_BLOCKS) run the human MLP head;
// blocks [HH_BLOCKS, HH_BLOCKS+2048) run the attention pooling pipeline.
// Head blocks launch first and drain under the attn memory stream.
// ---------------------------------------------------------------------------
#define TR 32
#define NT 8
#define ATTN_SMEM_BYTES (2*TR*256*4 + 2*TR*3*4 + 32*16)  // 66816

__global__ void __launch_bounds__(256, 3)
fused_kernel(const float* __restrict__ feats,
             const float* __restrict__ xyz,
             const float* __restrict__ hq,
             const float* __restrict__ W1,
             const float* __restrict__ b1,
             const float* __restrict__ W2,
             const float* __restrict__ b2,
             float* __restrict__ out) {
    extern __shared__ float sm[];
    const int t = threadIdx.x;
    const int warp = t >> 5;
    const int lane = t & 31;

    if (blockIdx.x < HH_BLOCKS) {
        // ================= human head: 4 rows per block =================
        const int blk = blockIdx.x;
        float* xs = sm;                                        // 1024 floats
        float4* part4 = reinterpret_cast<float4*>(sm + 1024);  // 1024 float4

        const float* src = hq + (size_t)blk * 4 * D_MODEL;
#pragma unroll
        for (int j = 0; j < 4; j++) xs[t + j * 256] = src[t + j * 256];
        __syncthreads();

        const int i0 = warp * 32;
        const float4* w1v = reinterpret_cast<const float4*>(W1);
        float4 a0 = {0,0,0,0}, a1 = {0,0,0,0}, a2 = {0,0,0,0}, a3 = {0,0,0,0};
#pragma unroll 4
        for (int ii = 0; ii < 32; ii++) {
            const int i = i0 + ii;
            const float4 wv = w1v[i * 32 + lane];
            const float x0 = xs[i];
            const float x1 = xs[256 + i];
            const float x2 = xs[512 + i];
            const float x3 = xs[768 + i];
            a0.x = fmaf(x0, wv.x, a0.x); a0.y = fmaf(x0, wv.y, a0.y);
            a0.z = fmaf(x0, wv.z, a0.z); a0.w = fmaf(x0, wv.w, a0.w);
            a1.x = fmaf(x1, wv.x, a1.x); a1.y = fmaf(x1, wv.y, a1.y);
            a1.z = fmaf(x1, wv.z, a1.z); a1.w = fmaf(x1, wv.w, a1.w);
            a2.x = fmaf(x2, wv.x, a2.x); a2.y = fmaf(x2, wv.y, a2.y);
            a2.z = fmaf(x2, wv.z, a2.z); a2.w = fmaf(x2, wv.w, a2.w);
            a3.x = fmaf(x3, wv.x, a3.x); a3.y = fmaf(x3, wv.y, a3.y);
            a3.z = fmaf(x3, wv.z, a3.z); a3.w = fmaf(x3, wv.w, a3.w);
        }
        part4[(warp * 4 + 0) * 32 + lane] = a0;
        part4[(warp * 4 + 1) * 32 + lane] = a1;
        part4[(warp * 4 + 2) * 32 + lane] = a2;
        part4[(warp * 4 + 3) * 32 + lane] = a3;
        __syncthreads();

        if (t < 128) {
            const int r = t >> 5;
            const int l = t & 31;
            float4 s = part4[r * 32 + l];
#pragma unroll
            for (int j = 1; j < 8; j++) {
                const float4 p = part4[(j * 4 + r) * 32 + l];
                s.x += p.x; s.y += p.y; s.z += p.z; s.w += p.w;
            }
            const float4 bb = reinterpret_cast<const float4*>(b1)[l];
            s.x = fmaxf(s.x + bb.x, 0.0f);
            s.y = fmaxf(s.y + bb.y, 0.0f);
            s.z = fmaxf(s.z + bb.z, 0.0f);
            s.w = fmaxf(s.w + bb.w, 0.0f);
            const float4 w2 = reinterpret_cast<const float4*>(W2)[l];
            float v = s.x * w2.x + s.y * w2.y + s.z * w2.z + s.w * w2.w;
#pragma unroll
            for (int off = 16; off > 0; off >>= 1)
                v += __shfl_xor_sync(0xffffffffu, v, off);
            if (l == 0) {
                const int row = blk * 4 + r;
                const float logit = v + b2[0];
                out[OUT_LOGITS + row] = logit;
                out[OUT_PROBS + row] = 1.0f / (1.0f + __expf(-logit));
            }
        }
        return;
    }

    // ================= attention pooling =================
    const int abx = blockIdx.x - HH_BLOCKS;   // 0..2047
    const int b = abx >> 7;                   // batch 0..15
    const int xt = abx & 127;                 // x-tile 0..127
    const int row0 = xt * (TR * NT);

    float* buf = sm;                              // 2 * 8192 floats
    float* xyzs = sm + 2 * TR * 256;              // 2 * 96 floats
    float4* red4 = reinterpret_cast<float4*>(sm + 2 * TR * 256 + 2 * TR * 3);

    const float4* q4 =
        reinterpret_cast<const float4*>(g_q + (size_t)b * K_DIM * D_MODEL);
    float4 qa[K_DIM], qb[K_DIM];
#pragma unroll
    for (int k = 0; k < K_DIM; k++) {
        qa[k] = q4[k * 64 + lane];
        qb[k] = q4[k * 64 + 32 + lane];
    }

    const float* fbase = feats + ((size_t)b * N_DIM + row0) * D_MODEL;
    const float* xbase = xyz + ((size_t)b * N_DIM + row0) * 3;

    // prologue: issue tiles 0 and 1
#pragma unroll
    for (int pt = 0; pt < 2; pt++) {
        const float* src = fbase + pt * TR * 256;
        float* dst = buf + pt * TR * 256;
#pragma unroll
        for (int j = 0; j < 8; j++) {
            const int f = (t + j * 256) * 4;
            cp16(dst + f, src + f);
        }
        if (t < TR * 3) cp4(xyzs + pt * TR * 3 + t, xbase + pt * TR * 3 + t);
        cp_commit();
    }

    float aw = 0.0f, ax = 0.0f, ay = 0.0f, az = 0.0f;
    const int myrow = (lane >> 2) & 3;

#pragma unroll 1
    for (int tile = 0; tile < NT; tile++) {
        if (tile < NT - 1) asm volatile("cp.async.wait_group 1;");
        else               asm volatile("cp.async.wait_group 0;");
        __syncthreads();

        const int bi = tile & 1;
        const float4* B4 = reinterpret_cast<const float4*>(buf + bi * TR * 256);
        const float* XZ = xyzs + bi * TR * 3;

        float keep = 0.0f;
#pragma unroll
        for (int rb = 0; rb < 4; rb++) {
            const int row = warp * 4 + rb;
            const float4 fa = B4[row * 64 + lane];
            const float4 fb = B4[row * 64 + 32 + lane];

            float p0, p1, p2, p3;
            p0 = fa.x * qa[0].x; p0 = fmaf(fa.y, qa[0].y, p0);
            p0 = fmaf(fa.z, qa[0].z, p0); p0 = fmaf(fa.w, qa[0].w, p0);
            p0 = fmaf(fb.x, qb[0].x, p0); p0 = fmaf(fb.y, qb[0].y, p0);
            p0 = fmaf(fb.z, qb[0].z, p0); p0 = fmaf(fb.w, qb[0].w, p0);

            p1 = fa.x * qa[1].x; p1 = fmaf(fa.y, qa[1].y, p1);
            p1 = fmaf(fa.z, qa[1].z, p1); p1 = fmaf(fa.w, qa[1].w, p1);
            p1 = fmaf(fb.x, qb[1].x, p1); p1 = fmaf(fb.y, qb[1].y, p1);
            p1 = fmaf(fb.z, qb[1].z, p1); p1 = fmaf(fb.w, qb[1].w, p1);

            p2 = fa.x * qa[2].x; p2 = fmaf(fa.y, qa[2].y, p2);
            p2 = fmaf(fa.z, qa[2].z, p2); p2 = fmaf(fa.w, qa[2].w, p2);
            p2 = fmaf(fb.x, qb[2].x, p2); p2 = fmaf(fb.y, qb[2].y, p2);
            p2 = fmaf(fb.z, qb[2].z, p2); p2 = fmaf(fb.w, qb[2].w, p2);

            p3 = fa.x * qa[3].x; p3 = fmaf(fa.y, qa[3].y, p3);
            p3 = fmaf(fa.z, qa[3].z, p3); p3 = fmaf(fa.w, qa[3].w, p3);
            p3 = fmaf(fb.x, qb[3].x, p3); p3 = fmaf(fb.y, qb[3].y, p3);
            p3 = fmaf(fb.w, qb[3].w, fmaf(fb.z, qb[3].z, p3));

            float t1 = (lane & 1) ? p0 : p1;
            t1 = __shfl_xor_sync(0xffffffffu, t1, 1);
            float t2 = (lane & 1) ? p2 : p3;
            t2 = __shfl_xor_sync(0xffffffffu, t2, 1);
            const float aab = ((lane & 1) ? p1 : p0) + t1;
            const float ccd = ((lane & 1) ? p3 : p2) + t2;
            float t3 = (lane & 2) ? aab : ccd;
            t3 = __shfl_xor_sync(0xffffffffu, t3, 2);
            float v = ((lane & 2) ? ccd : aab) + t3;
            v += __shfl_xor_sync(0xffffffffu, v, 4);
            v += __shfl_xor_sync(0xffffffffu, v, 8);
            v += __shfl_xor_sync(0xffffffffu, v, 16);
            if (myrow == rb) keep = v;
        }

        const float wgt = __expf(keep * LOGIT_SCALE);
        if (lane < 16) {
            const int row = warp * 4 + myrow;
            const float px = XZ[row * 3 + 0];
            const float py = XZ[row * 3 + 1];
            const float pz = XZ[row * 3 + 2];
            aw += wgt;
            ax = fmaf(wgt, px, ax);
            ay = fmaf(wgt, py, ay);
            az = fmaf(wgt, pz, az);
        }

        __syncthreads();

        if (tile + 2 < NT) {
            const float* src = fbase + (tile + 2) * TR * 256;
            float* dst = buf + bi * TR * 256;
#pragma unroll
            for (int j = 0; j < 8; j++) {
                const int f = (t + j * 256) * 4;
                cp16(dst + f, src + f);
            }
            if (t < TR * 3)
                cp4(xyzs + bi * TR * 3 + t, xbase + (tile + 2) * TR * 3 + t);
            cp_commit();
        }
    }

#pragma unroll
    for (int off = 4; off < 32; off <<= 1) {
        aw += __shfl_xor_sync(0xffffffffu, aw, off);
        ax += __shfl_xor_sync(0xffffffffu, ax, off);
        ay += __shfl_xor_sync(0xffffffffu, ay, off);
        az += __shfl_xor_sync(0xffffffffu, az, off);
    }
    if (lane < 4)
        red4[warp * 4 + lane] = make_float4(aw, ax, ay, az);
    __syncthreads();

    if (t < 16) {
        const int k = t >> 2;
        const int c = t & 3;
        const float* rf = reinterpret_cast<const float*>(red4);
        float s = 0.0f;
#pragma unroll
        for (int j = 0; j < 8; j++) s += rf[(j * 4 + k) * 4 + c];
        atomicAdd(&g_acc[((size_t)b * K_DIM + k) * 4 + c], s);
    }
}

// ---------------------------------------------------------------------------
// Kernel 3: finalize coords = (sum w*xyz) / (sum w)
// ---------------------------------------------------------------------------
__global__ void finalize_kernel(float* __restrict__ out) {
    const int t = threadIdx.x;  // 0..63 = (b*4 + k)
    if (t < B_DIM * K_DIM) {
        const float* g = g_acc + (size_t)t * 4;
        const float inv = 1.0f / g[0];
        out[OUT_COORDS + t * 3 + 0] = g[1] * inv;
        out[OUT_COORDS + t * 3 + 1] = g[2] * inv;
        out[OUT_COORDS + t * 3 + 2] = g[3] * inv;
    }
}

// ---------------------------------------------------------------------------
extern "C" void kernel_launch(void* const* d_in, const int* in_sizes, int n_in,
                              void* d_out, int out_size) {
    const float* hq    = (const float*)d_in[0];
    const float* oq    = (const float*)d_in[1];
    const float* feats = (const float*)d_in[2];
    const float* xyz   = (const float*)d_in[3];
    const float* W1    = (const float*)d_in[4];
    const float* b1    = (const float*)d_in[5];
    const float* W2    = (const float*)d_in[6];
    const float* b2    = (const float*)d_in[7];
    const float* Wq    = (const float*)d_in[8];
    const float* bq    = (const float*)d_in[9];
    float* out = (float*)d_out;

    cudaFuncSetAttribute(fused_kernel,
                         cudaFuncAttributeMaxDynamicSharedMemorySize,
                         ATTN_SMEM_BYTES);

    qproj_kernel<<<QP_BLOCKS, 256>>>(oq, Wq, bq);

    fused_kernel<<<HH_BLOCKS + ATTN_BLOCKS, 256, ATTN_SMEM_BYTES>>>(
        feats, xyz, hq, W1, b1, W2, b2, out);

    finalize_kernel<<<1, 64>>>(out);
}

// round 6
// speedup vs baseline: 1.9926x; 1.0166x over previous
#include <cuda_runtime.h>
#include <cuda_bf16.h>
#include <cstdint>

// Problem constants
#define B_DIM 16
#define P_DIM 87
#define K_DIM 4
#define N_DIM 32768
#define D_MODEL 256
#define HIDDEN 128
#define LOGIT_SCALE 0.125f   // ATTN_SCALE / TAU

// Output layout (flattened tuple, fp32)
#define OUT_PROBS 0
#define OUT_LOGITS 1392
#define OUT_COORDS 2784

// Scratch (no allocations allowed -> __device__ globals)
__device__ float g_q[B_DIM * K_DIM * D_MODEL];   // projected queries
__device__ float g_acc[B_DIM * K_DIM * 4];       // per (b,k): sumw, sx, sy, sz
__device__ int   g_done = 0;                     // qproj completion counter

#define QP_BLOCKS 16        // q-proj blocks, 4 rows each = 64 rows
#define HH_BLOCKS 348       // human-head blocks, 4 rows each = 1392 rows
#define ATTN_BLOCKS 2048    // 128 x-tiles * 16 batches
#define ATTN_BASE (QP_BLOCKS + HH_BLOCKS)   // 364

// ---------------------------------------------------------------------------
// cp.async helpers
// ---------------------------------------------------------------------------
__device__ __forceinline__ void cp16(void* dst, const void* src) {
    uint32_t d = (uint32_t)__cvta_generic_to_shared(dst);
    asm volatile("cp.async.cg.shared.global [%0], [%1], 16;" :: "r"(d), "l"(src));
}
__device__ __forceinline__ void cp4(void* dst, const void* src) {
    uint32_t d = (uint32_t)__cvta_generic_to_shared(dst);
    asm volatile("cp.async.ca.shared.global [%0], [%1], 4;" :: "r"(d), "l"(src));
}
__device__ __forceinline__ void cp_commit() {
    asm volatile("cp.async.commit_group;");
}
__device__ __forceinline__ int ld_acquire(const int* p) {
    int v;
    asm volatile("ld.acquire.gpu.global.b32 %0, [%1];" : "=r"(v) : "l"(p));
    return v;
}

// ---------------------------------------------------------------------------
// Fused kernel:
//   blocks [0, 16):        q projection (+ g_acc zeroing), release g_done
//   blocks [16, 364):      human MLP head
//   blocks [364, 2412):    attention pooling (prefetch, acquire-spin, mainloop)
// ---------------------------------------------------------------------------
#define TR 32
#define NT 8
#define ATTN_SMEM_BYTES (2*TR*256*4 + 2*TR*3*4 + 32*16)  // 66816

__global__ void __launch_bounds__(256, 3)
fused_kernel(const float* __restrict__ feats,
             const float* __restrict__ xyz,
             const float* __restrict__ hq,
             const float* __restrict__ oq,
             const float* __restrict__ W1,
             const float* __restrict__ b1,
             const float* __restrict__ W2,
             const float* __restrict__ b2,
             const float* __restrict__ Wq,
             const float* __restrict__ bq,
             float* __restrict__ out) {
    extern __shared__ float sm[];
    const int t = threadIdx.x;
    const int warp = t >> 5;
    const int lane = t & 31;

    if (blockIdx.x < QP_BLOCKS) {
        // ================= q projection: 4 rows per block =================
        const int qb = blockIdx.x;
        float* xs = sm;                                        // 1024 floats
        float4* part4 = reinterpret_cast<float4*>(sm + 1024);  // 1024 float4

        const float* src = oq + (size_t)qb * 4 * D_MODEL;
#pragma unroll
        for (int j = 0; j < 4; j++) xs[t + j * 256] = src[t + j * 256];
        if (qb == 0) g_acc[t] = 0.0f;    // 256 floats == blockDim
        __syncthreads();

        const int i0 = warp * 32;
        const float4* wqv = reinterpret_cast<const float4*>(Wq);
        float4 aA[4], aB[4];
#pragma unroll
        for (int r = 0; r < 4; r++) { aA[r] = {0,0,0,0}; aB[r] = {0,0,0,0}; }
#pragma unroll 4
        for (int ii = 0; ii < 32; ii++) {
            const int i = i0 + ii;
            const float4 wa = wqv[i * 64 + lane];
            const float4 wb = wqv[i * 64 + 32 + lane];
            const float x0 = xs[i];
            const float x1 = xs[256 + i];
            const float x2 = xs[512 + i];
            const float x3 = xs[768 + i];
            aA[0].x = fmaf(x0, wa.x, aA[0].x); aA[0].y = fmaf(x0, wa.y, aA[0].y);
            aA[0].z = fmaf(x0, wa.z, aA[0].z); aA[0].w = fmaf(x0, wa.w, aA[0].w);
            aB[0].x = fmaf(x0, wb.x, aB[0].x); aB[0].y = fmaf(x0, wb.y, aB[0].y);
            aB[0].z = fmaf(x0, wb.z, aB[0].z); aB[0].w = fmaf(x0, wb.w, aB[0].w);
            aA[1].x = fmaf(x1, wa.x, aA[1].x); aA[1].y = fmaf(x1, wa.y, aA[1].y);
            aA[1].z = fmaf(x1, wa.z, aA[1].z); aA[1].w = fmaf(x1, wa.w, aA[1].w);
            aB[1].x = fmaf(x1, wb.x, aB[1].x); aB[1].y = fmaf(x1, wb.y, aB[1].y);
            aB[1].z = fmaf(x1, wb.z, aB[1].z); aB[1].w = fmaf(x1, wb.w, aB[1].w);
            aA[2].x = fmaf(x2, wa.x, aA[2].x); aA[2].y = fmaf(x2, wa.y, aA[2].y);
            aA[2].z = fmaf(x2, wa.z, aA[2].z); aA[2].w = fmaf(x2, wa.w, aA[2].w);
            aB[2].x = fmaf(x2, wb.x, aB[2].x); aB[2].y = fmaf(x2, wb.y, aB[2].y);
            aB[2].z = fmaf(x2, wb.z, aB[2].z); aB[2].w = fmaf(x2, wb.w, aB[2].w);
            aA[3].x = fmaf(x3, wa.x, aA[3].x); aA[3].y = fmaf(x3, wa.y, aA[3].y);
            aA[3].z = fmaf(x3, wa.z, aA[3].z); aA[3].w = fmaf(x3, wa.w, aA[3].w);
            aB[3].x = fmaf(x3, wb.x, aB[3].x); aB[3].y = fmaf(x3, wb.y, aB[3].y);
            aB[3].z = fmaf(x3, wb.z, aB[3].z); aB[3].w = fmaf(x3, wb.w, aB[3].w);
        }
#pragma unroll
        for (int r = 0; r < 4; r++) {
            part4[(warp * 4 + r) * 64 + lane] = aA[r];
            part4[(warp * 4 + r) * 64 + 32 + lane] = aB[r];
        }
        __syncthreads();

        const int r = t >> 6;
        const int c = t & 63;
        float4 s = part4[r * 64 + c];
#pragma unroll
        for (int j = 1; j < 8; j++) {
            const float4 p = part4[(j * 4 + r) * 64 + c];
            s.x += p.x; s.y += p.y; s.z += p.z; s.w += p.w;
        }
        const float4 bb = reinterpret_cast<const float4*>(bq)[c];
        s.x += bb.x; s.y += bb.y; s.z += bb.z; s.w += bb.w;
        reinterpret_cast<float4*>(g_q + (size_t)(qb * 4 + r) * D_MODEL)[c] = s;

        // release: make g_q (and g_acc zeroing) visible, then count
        __syncthreads();
        if (t == 0) {
            __threadfence();
            atomicAdd(&g_done, 1);
        }
        return;
    }

    if (blockIdx.x < ATTN_BASE) {
        // ================= human head: 4 rows per block =================
        const int blk = blockIdx.x - QP_BLOCKS;
        float* xs = sm;
        float4* part4 = reinterpret_cast<float4*>(sm + 1024);

        const float* src = hq + (size_t)blk * 4 * D_MODEL;
#pragma unroll
        for (int j = 0; j < 4; j++) xs[t + j * 256] = src[t + j * 256];
        __syncthreads();

        const int i0 = warp * 32;
        const float4* w1v = reinterpret_cast<const float4*>(W1);
        float4 a0 = {0,0,0,0}, a1 = {0,0,0,0}, a2 = {0,0,0,0}, a3 = {0,0,0,0};
#pragma unroll 4
        for (int ii = 0; ii < 32; ii++) {
            const int i = i0 + ii;
            const float4 wv = w1v[i * 32 + lane];
            const float x0 = xs[i];
            const float x1 = xs[256 + i];
            const float x2 = xs[512 + i];
            const float x3 = xs[768 + i];
            a0.x = fmaf(x0, wv.x, a0.x); a0.y = fmaf(x0, wv.y, a0.y);
            a0.z = fmaf(x0, wv.z, a0.z); a0.w = fmaf(x0, wv.w, a0.w);
            a1.x = fmaf(x1, wv.x, a1.x); a1.y = fmaf(x1, wv.y, a1.y);
            a1.z = fmaf(x1, wv.z, a1.z); a1.w = fmaf(x1, wv.w, a1.w);
            a2.x = fmaf(x2, wv.x, a2.x); a2.y = fmaf(x2, wv.y, a2.y);
            a2.z = fmaf(x2, wv.z, a2.z); a2.w = fmaf(x2, wv.w, a2.w);
            a3.x = fmaf(x3, wv.x, a3.x); a3.y = fmaf(x3, wv.y, a3.y);
            a3.z = fmaf(x3, wv.z, a3.z); a3.w = fmaf(x3, wv.w, a3.w);
        }
        part4[(warp * 4 + 0) * 32 + lane] = a0;
        part4[(warp * 4 + 1) * 32 + lane] = a1;
        part4[(warp * 4 + 2) * 32 + lane] = a2;
        part4[(warp * 4 + 3) * 32 + lane] = a3;
        __syncthreads();

        if (t < 128) {
            const int r = t >> 5;
            const int l = t & 31;
            float4 s = part4[r * 32 + l];
#pragma unroll
            for (int j = 1; j < 8; j++) {
                const float4 p = part4[(j * 4 + r) * 32 + l];
                s.x += p.x; s.y += p.y; s.z += p.z; s.w += p.w;
            }
            const float4 bb = reinterpret_cast<const float4*>(b1)[l];
            s.x = fmaxf(s.x + bb.x, 0.0f);
            s.y = fmaxf(s.y + bb.y, 0.0f);
            s.z = fmaxf(s.z + bb.z, 0.0f);
            s.w = fmaxf(s.w + bb.w, 0.0f);
            const float4 w2 = reinterpret_cast<const float4*>(W2)[l];
            float v = s.x * w2.x + s.y * w2.y + s.z * w2.z + s.w * w2.w;
#pragma unroll
            for (int off = 16; off > 0; off >>= 1)
                v += __shfl_xor_sync(0xffffffffu, v, off);
            if (l == 0) {
                const int row = blk * 4 + r;
                const float logit = v + b2[0];
                out[OUT_LOGITS + row] = logit;
                out[OUT_PROBS + row] = 1.0f / (1.0f + __expf(-logit));
            }
        }
        return;
    }

    // ================= attention pooling =================
    const int abx = blockIdx.x - ATTN_BASE;   // 0..2047
    const int b = abx >> 7;                   // batch 0..15
    const int xt = abx & 127;                 // x-tile 0..127
    const int row0 = xt * (TR * NT);

    float* buf = sm;                              // 2 * 8192 floats
    float* xyzs = sm + 2 * TR * 256;              // 2 * 96 floats
    float4* red4 = reinterpret_cast<float4*>(sm + 2 * TR * 256 + 2 * TR * 3);

    const float* fbase = feats + ((size_t)b * N_DIM + row0) * D_MODEL;
    const float* xbase = xyz + ((size_t)b * N_DIM + row0) * 3;

    // prologue FIRST (independent of g_q): issue tiles 0 and 1
#pragma unroll
    for (int pt = 0; pt < 2; pt++) {
        const float* src = fbase + pt * TR * 256;
        float* dst = buf + pt * TR * 256;
#pragma unroll
        for (int j = 0; j < 8; j++) {
            const int f = (t + j * 256) * 4;
            cp16(dst + f, src + f);
        }
        if (t < TR * 3) cp4(xyzs + pt * TR * 3 + t, xbase + pt * TR * 3 + t);
        cp_commit();
    }

    // acquire-spin until q projection is complete (overlaps tile-0 DRAM fetch)
    if (t == 0) {
        while (ld_acquire(&g_done) < QP_BLOCKS)
            __nanosleep(64);
    }
    __syncthreads();

    const float4* q4 =
        reinterpret_cast<const float4*>(g_q + (size_t)b * K_DIM * D_MODEL);
    float4 qa[K_DIM], qb[K_DIM];
#pragma unroll
    for (int k = 0; k < K_DIM; k++) {
        qa[k] = q4[k * 64 + lane];
        qb[k] = q4[k * 64 + 32 + lane];
    }

    float aw = 0.0f, ax = 0.0f, ay = 0.0f, az = 0.0f;
    const int myrow = (lane >> 2) & 3;

#pragma unroll 1
    for (int tile = 0; tile < NT; tile++) {
        if (tile < NT - 1) asm volatile("cp.async.wait_group 1;");
        else               asm volatile("cp.async.wait_group 0;");
        __syncthreads();

        const int bi = tile & 1;
        const float4* B4 = reinterpret_cast<const float4*>(buf + bi * TR * 256);
        const float* XZ = xyzs + bi * TR * 3;

        float keep = 0.0f;
#pragma unroll
        for (int rb = 0; rb < 4; rb++) {
            const int row = warp * 4 + rb;
            const float4 fa = B4[row * 64 + lane];
            const float4 fb = B4[row * 64 + 32 + lane];

            float p0, p1, p2, p3;
            p0 = fa.x * qa[0].x; p0 = fmaf(fa.y, qa[0].y, p0);
            p0 = fmaf(fa.z, qa[0].z, p0); p0 = fmaf(fa.w, qa[0].w, p0);
            p0 = fmaf(fb.x, qb[0].x, p0); p0 = fmaf(fb.y, qb[0].y, p0);
            p0 = fmaf(fb.z, qb[0].z, p0); p0 = fmaf(fb.w, qb[0].w, p0);

            p1 = fa.x * qa[1].x; p1 = fmaf(fa.y, qa[1].y, p1);
            p1 = fmaf(fa.z, qa[1].z, p1); p1 = fmaf(fa.w, qa[1].w, p1);
            p1 = fmaf(fb.x, qb[1].x, p1); p1 = fmaf(fb.y, qb[1].y, p1);
            p1 = fmaf(fb.z, qb[1].z, p1); p1 = fmaf(fb.w, qb[1].w, p1);

            p2 = fa.x * qa[2].x; p2 = fmaf(fa.y, qa[2].y, p2);
            p2 = fmaf(fa.z, qa[2].z, p2); p2 = fmaf(fa.w, qa[2].w, p2);
            p2 = fmaf(fb.x, qb[2].x, p2); p2 = fmaf(fb.y, qb[2].y, p2);
            p2 = fmaf(fb.z, qb[2].z, p2); p2 = fmaf(fb.w, qb[2].w, p2);

            p3 = fa.x * qa[3].x; p3 = fmaf(fa.y, qa[3].y, p3);
            p3 = fmaf(fa.z, qa[3].z, p3); p3 = fmaf(fa.w, qa[3].w, p3);
            p3 = fmaf(fb.x, qb[3].x, p3); p3 = fmaf(fb.y, qb[3].y, p3);
            p3 = fmaf(fb.w, qb[3].w, fmaf(fb.z, qb[3].z, p3));

            float t1 = (lane & 1) ? p0 : p1;
            t1 = __shfl_xor_sync(0xffffffffu, t1, 1);
            float t2 = (lane & 1) ? p2 : p3;
            t2 = __shfl_xor_sync(0xffffffffu, t2, 1);
            const float aab = ((lane & 1) ? p1 : p0) + t1;
            const float ccd = ((lane & 1) ? p3 : p2) + t2;
            float t3 = (lane & 2) ? aab : ccd;
            t3 = __shfl_xor_sync(0xffffffffu, t3, 2);
            float v = ((lane & 2) ? ccd : aab) + t3;
            v += __shfl_xor_sync(0xffffffffu, v, 4);
            v += __shfl_xor_sync(0xffffffffu, v, 8);
            v += __shfl_xor_sync(0xffffffffu, v, 16);
            if (myrow == rb) keep = v;
        }

        const float wgt = __expf(keep * LOGIT_SCALE);
        if (lane < 16) {
            const int row = warp * 4 + myrow;
            const float px = XZ[row * 3 + 0];
            const float py = XZ[row * 3 + 1];
            const float pz = XZ[row * 3 + 2];
            aw += wgt;
            ax = fmaf(wgt, px, ax);
            ay = fmaf(wgt, py, ay);
            az = fmaf(wgt, pz, az);
        }

        __syncthreads();

        if (tile + 2 < NT) {
            const float* src = fbase + (tile + 2) * TR * 256;
            float* dst = buf + bi * TR * 256;
#pragma unroll
            for (int j = 0; j < 8; j++) {
                const int f = (t + j * 256) * 4;
                cp16(dst + f, src + f);
            }
            if (t < TR * 3)
                cp4(xyzs + bi * TR * 3 + t, xbase + (tile + 2) * TR * 3 + t);
            cp_commit();
        }
    }

#pragma unroll
    for (int off = 4; off < 32; off <<= 1) {
        aw += __shfl_xor_sync(0xffffffffu, aw, off);
        ax += __shfl_xor_sync(0xffffffffu, ax, off);
        ay += __shfl_xor_sync(0xffffffffu, ay, off);
        az += __shfl_xor_sync(0xffffffffu, az, off);
    }
    if (lane < 4)
        red4[warp * 4 + lane] = make_float4(aw, ax, ay, az);
    __syncthreads();

    if (t < 16) {
        const int k = t >> 2;
        const int c = t & 3;
        const float* rf = reinterpret_cast<const float*>(red4);
        float s = 0.0f;
#pragma unroll
        for (int j = 0; j < 8; j++) s += rf[(j * 4 + k) * 4 + c];
        atomicAdd(&g_acc[((size_t)b * K_DIM + k) * 4 + c], s);
    }
}

// ---------------------------------------------------------------------------
// Finalize: coords = (sum w*xyz) / (sum w); also resets g_done for the next
// graph replay.
// ---------------------------------------------------------------------------
__global__ void finalize_kernel(float* __restrict__ out) {
    const int t = threadIdx.x;  // 0..63 = (b*4 + k)
    if (t < B_DIM * K_DIM) {
        const float* g = g_acc + (size_t)t * 4;
        const float inv = 1.0f / g[0];
        out[OUT_COORDS + t * 3 + 0] = g[1] * inv;
        out[OUT_COORDS + t * 3 + 1] = g[2] * inv;
        out[OUT_COORDS + t * 3 + 2] = g[3] * inv;
    }
    if (t == 0) g_done = 0;
}

// ---------------------------------------------------------------------------
extern "C" void kernel_launch(void* const* d_in, const int* in_sizes, int n_in,
                              void* d_out, int out_size) {
    const float* hq    = (const float*)d_in[0];
    const float* oq    = (const float*)d_in[1];
    const float* feats = (const float*)d_in[2];
    const float* xyz   = (const float*)d_in[3];
    const float* W1    = (const float*)d_in[4];
    const float* b1    = (const float*)d_in[5];
    const float* W2    = (const float*)d_in[6];
    const float* b2    = (const float*)d_in[7];
    const float* Wq    = (const float*)d_in[8];
    const float* bq    = (const float*)d_in[9];
    float* out = (float*)d_out;

    cudaFuncSetAttribute(fused_kernel,
                         cudaFuncAttributeMaxDynamicSharedMemorySize,
                         ATTN_SMEM_BYTES);

    fused_kernel<<<QP_BLOCKS + HH_BLOCKS + ATTN_BLOCKS, 256, ATTN_SMEM_BYTES>>>(
        feats, xyz, hq, oq, W1, b1, W2, b2, Wq, bq, out);

    finalize_kernel<<<1, 64>>>(out);
}